// round 7
// baseline (speedup 1.0000x reference)
#include <cuda_runtime.h>

#define BB 1024
#define TT 128
#define KK 128
#define START_TAG 126
#define STOP_TAG 127

// Per-warp length from the monotone mask row. Mask dtype detected from first word.
__device__ __forceinline__ int warp_len(const void* masks, int b, int lane) {
    unsigned w0 = *(const unsigned*)masks;
    int cnt;
    if (w0 == 0x01010101u) {
        unsigned v = ((const unsigned*)((const char*)masks + (size_t)b * TT))[lane];
        cnt = __popc(v & 0x01010101u);
    } else if (w0 == 0x3F800000u) {
        float4 v = ((const float4*)((const float*)masks + (size_t)b * TT))[lane];
        cnt = (v.x != 0.0f) + (v.y != 0.0f) + (v.z != 0.0f) + (v.w != 0.0f);
    } else {
        int4 v = ((const int4*)((const int*)masks + (size_t)b * TT))[lane];
        cnt = (v.x != 0) + (v.y != 0) + (v.z != 0) + (v.w != 0);
    }
    return __reduce_add_sync(0xffffffffu, cnt);
}

// Per-batch Viterbi state (2 per warp, interleaved chains for ILP)
struct BS {
    float v0, v1, v2, v3;      // partition (lane owns cur = 4*lane..4*lane+3)
    float s0, s1, s2, s3;      // snapshot at t == last
    const float4* fb4;         // feat rows (32 float4 per row)
    unsigned char* bp;         // backpointers, 16 KB
    uint2* cand;               // staging, 2 x 132 records
    int last;
    float4 r0, r1;             // feat prefetch ring, depth 2
};

// Phase 1: threshold + ballots + candidate compaction (no syncwarp inside)
__device__ __forceinline__ void step_pre(BS& S, int t, float delta, int lane,
                                         unsigned lmask, int& ncand_o, uint2*& cb_o) {
    // all partitions > -12 (v >= M-6, M >= ~2): +64 bias makes bits uint-monotone
    float lm = fmaxf(fmaxf(S.v0, S.v1), fmaxf(S.v2, S.v3));
    unsigned mu = __reduce_max_sync(0xffffffffu, __float_as_uint(lm + 64.0f));
    float thr = (__uint_as_float(mu) - 64.0f) - delta;   // bias ulp < delta margin

    unsigned c0 = __ballot_sync(0xffffffffu, S.v0 >= thr);
    unsigned c1 = __ballot_sync(0xffffffffu, S.v1 >= thr);
    unsigned c2 = __ballot_sync(0xffffffffu, S.v2 >= thr);
    unsigned c3 = __ballot_sync(0xffffffffu, S.v3 >= thr);
    int n0 = __popc(c0), n01 = n0 + __popc(c1), n012 = n01 + __popc(c2);
    int nc = n012 + __popc(c3);

    // compact (pv, prev) comp-major (prev = 0,4,..,124, 1,5,..) — same order as prior rounds
    uint2* cb = S.cand + ((t & 1) ? 132 : 0);
    int p0 = lane * 4;
    if ((c0 >> lane) & 1u) cb[       __popc(c0 & lmask)] = make_uint2(__float_as_uint(S.v0), p0 + 0);
    if ((c1 >> lane) & 1u) cb[n0   + __popc(c1 & lmask)] = make_uint2(__float_as_uint(S.v1), p0 + 1);
    if ((c2 >> lane) & 1u) cb[n01  + __popc(c2 & lmask)] = make_uint2(__float_as_uint(S.v2), p0 + 2);
    if ((c3 >> lane) & 1u) cb[n012 + __popc(c3 & lmask)] = make_uint2(__float_as_uint(S.v3), p0 + 3);
    if (lane < 3)          cb[nc + lane] = make_uint2(0xFF7FFFFFu, 0);   // -FLT_MAX pad
    ncand_o = nc; cb_o = cb;
}

// Phase 2: fixed-shape candidate loop + backpointer store + v update + snapshot
__device__ __forceinline__ void step_post(BS& S, int t, float4 fc, int ncand,
                                          const uint2* cb, const float4* ts4, int lane) {
    float b0 = -3.4e38f, b1 = -3.4e38f, b2 = -3.4e38f, b3 = -3.4e38f;
    int   i0 = 0, i1 = 0, i2 = 0, i3 = 0;
    int ng = (ncand + 3) >> 2;
    const uint4* cb4 = (const uint4*)cb;
    #pragma unroll 2
    for (int g = 0; g < ng; g++) {
        uint4 ra = cb4[2 * g];
        uint4 rb = cb4[2 * g + 1];
        #define PROC(PVU, PREV)                                                      \
        {   float pv = __uint_as_float(PVU); int prev = (int)(PREV);                 \
            float4 tr = ts4[prev * 32 + lane];                                       \
            float q0 = (pv + tr.x) + fc.x; if (q0 > b0) { b0 = q0; i0 = prev; }      \
            float q1 = (pv + tr.y) + fc.y; if (q1 > b1) { b1 = q1; i1 = prev; }      \
            float q2 = (pv + tr.z) + fc.z; if (q2 > b2) { b2 = q2; i2 = prev; }      \
            float q3 = (pv + tr.w) + fc.w; if (q3 > b3) { b3 = q3; i3 = prev; }      \
        }
        PROC(ra.x, ra.y) PROC(ra.z, ra.w) PROC(rb.x, rb.y) PROC(rb.z, rb.w)
        #undef PROC
    }
    ((unsigned*)(S.bp + t * KK))[lane] =
        (unsigned)i0 | ((unsigned)i1 << 8) | ((unsigned)i2 << 16) | ((unsigned)i3 << 24);
    S.v0 = b0; S.v1 = b1; S.v2 = b2; S.v3 = b3;
    bool al = (t == S.last);
    S.s0 = al ? S.v0 : S.s0; S.s1 = al ? S.v1 : S.s1;
    S.s2 = al ? S.v2 : S.s2; S.s3 = al ? S.v3 : S.s3;
}

// STOP argmax from snapshot (first-index ties)
__device__ __forceinline__ int finish(const BS& S, const float* ts, int lane, float& score) {
    int p0 = lane * 4;
    float q0 = S.s0 + ts[(p0 + 0) * KK + STOP_TAG];
    float q1 = S.s1 + ts[(p0 + 1) * KK + STOP_TAG];
    float q2 = S.s2 + ts[(p0 + 2) * KK + STOP_TAG];
    float q3 = S.s3 + ts[(p0 + 3) * KK + STOP_TAG];
    float bv = q0; int bi = p0;
    if (q1 > bv) { bv = q1; bi = p0 + 1; }
    if (q2 > bv) { bv = q2; bi = p0 + 2; }
    if (q3 > bv) { bv = q3; bi = p0 + 3; }
    #pragma unroll
    for (int o = 16; o; o >>= 1) {
        float ov = __shfl_xor_sync(0xffffffffu, bv, o);
        int   oi = __shfl_xor_sync(0xffffffffu, bi, o);
        if (ov > bv || (ov == bv && oi < bi)) { bv = ov; bi = oi; }
    }
    score = bv;
    return bi;
}

// ---------------------------------------------------------------------------
// Fused Viterbi, 2 batches per warp (interleaved independent chains for ILP).
// 128 CTAs x 4 warps (1 warp/SMSP), 8 batches/CTA. Straight-line 127 steps.
// SMEM: 64KB trans + 8x16KB bp + 8x2112B staging = 213504 B -> 1 CTA/SM.
// ---------------------------------------------------------------------------
extern "C" __global__ void __launch_bounds__(128, 1)
viterbi_kernel(const float* __restrict__ feats,
               const float* __restrict__ trans,
               const void*  __restrict__ masks,
               float* __restrict__ out_score,
               float* __restrict__ out_dec) {
    extern __shared__ char smem[];
    float* ts = (float*)smem;                      // [prev*128 + cur], 64 KB
    __shared__ float s_wr[4];
    __shared__ float s_delta;

    int tid = threadIdx.x;

    for (int i = tid; i < KK * KK / 4; i += 128)
        ((float4*)ts)[i] = ((const float4*)trans)[i];
    __syncthreads();

    // Exact prune bound: Delta = max over cur of (max-min of trans[:,cur]) + margin
    {
        float mx = -3.4e38f, mn = 3.4e38f;
        #pragma unroll 8
        for (int p = 0; p < 128; p++) {
            float v = ts[p * 128 + tid];
            mx = fmaxf(mx, v); mn = fminf(mn, v);
        }
        float r = mx - mn;
        #pragma unroll
        for (int o = 16; o; o >>= 1) r = fmaxf(r, __shfl_xor_sync(0xffffffffu, r, o));
        if ((tid & 31) == 0) s_wr[tid >> 5] = r;
    }
    __syncthreads();
    if (tid == 0)
        s_delta = fmaxf(fmaxf(s_wr[0], s_wr[1]), fmaxf(s_wr[2], s_wr[3])) + 1e-3f;
    __syncthreads();
    float delta = s_delta;

    int w = tid >> 5, lane = tid & 31;
    unsigned lmask = (1u << lane) - 1u;
    const float4* ts4 = (const float4*)ts;

    int bA = blockIdx.x * 8 + w * 2;
    int bB = bA + 1;
    int ciA = w * 2, ciB = ciA + 1;                // batch index within CTA (0..7)

    BS A, B;
    A.fb4 = (const float4*)(feats + (size_t)bA * TT * KK);
    B.fb4 = (const float4*)(feats + (size_t)bB * TT * KK);
    A.bp = (unsigned char*)(smem + 65536 + ciA * (TT * KK));
    B.bp = (unsigned char*)(smem + 65536 + ciB * (TT * KK));
    A.cand = (uint2*)(smem + 65536 + 8 * TT * KK + ciA * 2112);
    B.cand = (uint2*)(smem + 65536 + 8 * TT * KK + ciB * 2112);
    A.last = warp_len(masks, bA, lane) - 1;        // >= 63
    B.last = warp_len(masks, bB, lane) - 1;

    // t = 0: partition = feats[:,0,:] + trans[START,:]
    {
        float4 tr0 = ((const float4*)(ts + START_TAG * KK))[lane];
        float4 fA = A.fb4[lane];
        float4 fB = B.fb4[lane];
        A.v0 = fA.x + tr0.x; A.v1 = fA.y + tr0.y; A.v2 = fA.z + tr0.z; A.v3 = fA.w + tr0.w;
        B.v0 = fB.x + tr0.x; B.v1 = fB.y + tr0.y; B.v2 = fB.z + tr0.z; B.v3 = fB.w + tr0.w;
        A.s0 = A.v0; A.s1 = A.v1; A.s2 = A.v2; A.s3 = A.v3;
        B.s0 = B.v0; B.s1 = B.v1; B.s2 = B.v2; B.s3 = B.v3;
    }
    A.r0 = A.fb4[1 * 32 + lane]; A.r1 = A.fb4[2 * 32 + lane];
    B.r0 = B.fb4[1 * 32 + lane]; B.r1 = B.fb4[2 * 32 + lane];

    // one step for both batches: pre(A), pre(B), one syncwarp, post(A), post(B)
    #define DO2(T, RR) {                                                        \
        float4 fA = A.RR; A.RR = A.fb4[min((T) + 2, 127) * 32 + lane];          \
        float4 fB = B.RR; B.RR = B.fb4[min((T) + 2, 127) * 32 + lane];          \
        int nA, nB; uint2 *cA, *cB2;                                            \
        step_pre(A, (T), delta, lane, lmask, nA, cA);                           \
        step_pre(B, (T), delta, lane, lmask, nB, cB2);                          \
        __syncwarp();                                                           \
        step_post(A, (T), fA, nA, cA, ts4, lane);                               \
        step_post(B, (T), fB, nB, cB2, ts4, lane);                              \
    }

    #pragma unroll 1
    for (int tb = 1; tb <= 125; tb += 2) {
        DO2(tb,     r0)
        DO2(tb + 1, r1)
    }
    DO2(127, r0)                                   // t = 1..127 total
    #undef DO2

    float scA, scB;
    int curA = finish(A, ts, lane, scA);
    int curB = finish(B, ts, lane, scB);

    if (out_score && lane == 0) { out_score[bA] = scA; out_score[bB] = scB; }

    if (out_dec) {
        float* odA = out_dec + (size_t)bA * TT;
        float* odB = out_dec + (size_t)bB * TT;
        for (int t = A.last + 1 + lane; t < TT - 1; t += 32) odA[t] = 0.0f;
        for (int t = B.last + 1 + lane; t < TT - 1; t += 32) odB[t] = 0.0f;
        if (lane == 0) {
            odA[TT - 1] = (float)curA; odA[A.last] = (float)curA;   // ref quirk
            odB[TT - 1] = (float)curB; odB[B.last] = (float)curB;
        }
        // interleaved SMEM pointer chases (independent, warp-uniform)
        for (int t = 127; t >= 1; t--) {
            if (t <= A.last) { curA = A.bp[t * KK + curA]; if (lane == 0) odA[t - 1] = (float)curA; }
            if (t <= B.last) { curB = B.bp[t * KK + curB]; if (lane == 0) odB[t - 1] = (float)curB; }
        }
    }
}

// ---------------------------------------------------------------------------
extern "C" void kernel_launch(void* const* d_in, const int* in_sizes, int n_in,
                              void* d_out, int out_size) {
    const float* feats = nullptr;
    const float* trans = nullptr;
    const void*  masks = nullptr;
    for (int i = 0; i < n_in; i++) {
        if      (in_sizes[i] == BB * TT * KK) feats = (const float*)d_in[i];
        else if (in_sizes[i] == KK * KK)      trans = (const float*)d_in[i];
        else if (in_sizes[i] == BB * TT)      masks = d_in[i];
    }
    if (!feats || !trans || !masks) return;

    float* out   = (float*)d_out;
    float* score = nullptr;
    float* dec   = nullptr;
    if (out_size == BB * TT + BB) { score = out; dec = out + BB; }   // (path_score, decode)
    else if (out_size == BB * TT) { dec = out; }
    else if (out_size == BB)      { score = out; }
    else                          { score = out; if (out_size >= BB * TT + BB) dec = out + BB; }

    int smem_bytes = 65536 + 8 * TT * KK + 8 * 2112;   // trans + bp + staging = 213504
    cudaFuncSetAttribute(viterbi_kernel, cudaFuncAttributeMaxDynamicSharedMemorySize, smem_bytes);
    viterbi_kernel<<<BB / 8, 128, smem_bytes>>>(feats, trans, masks, score, dec);
}

// round 8
// speedup vs baseline: 1.3417x; 1.3417x over previous
#include <cuda_runtime.h>

#define BB 1024
#define TT 128
#define KK 128
#define START_TAG 126
#define STOP_TAG 127

// Per-warp length from the monotone mask row. Mask dtype detected from first word.
__device__ __forceinline__ int warp_len(const void* masks, int b, int lane) {
    unsigned w0 = *(const unsigned*)masks;
    int cnt;
    if (w0 == 0x01010101u) {
        unsigned v = ((const unsigned*)((const char*)masks + (size_t)b * TT))[lane];
        cnt = __popc(v & 0x01010101u);
    } else if (w0 == 0x3F800000u) {
        float4 v = ((const float4*)((const float*)masks + (size_t)b * TT))[lane];
        cnt = (v.x != 0.0f) + (v.y != 0.0f) + (v.z != 0.0f) + (v.w != 0.0f);
    } else {
        int4 v = ((const int4*)((const int*)masks + (size_t)b * TT))[lane];
        cnt = (v.x != 0) + (v.y != 0) + (v.z != 0) + (v.w != 0);
    }
    return __reduce_add_sync(0xffffffffu, cnt);
}

// ---------------------------------------------------------------------------
// Fused Viterbi: warp per batch, lane owns cur/prev = {4*lane .. 4*lane+3}.
// Straight-line forward (127 steps for every warp, predicated t==last snapshot).
// Candidate records in SMEM padded with -FLT_MAX; records 0-7 processed
// straight-line (4x LDS.128 up front), uniform-branch loop for overflow.
// Warp max via +64 bias trick (positive floats are uint-monotone).
// SMEM: 64KB trans + 8x16KB bp + 8x2112B staging = 213504 -> 1 CTA/SM.
// ---------------------------------------------------------------------------
extern "C" __global__ void __launch_bounds__(256, 1)
viterbi_kernel(const float* __restrict__ feats,
               const float* __restrict__ trans,
               const void*  __restrict__ masks,
               float* __restrict__ out_score,
               float* __restrict__ out_dec) {
    extern __shared__ char smem[];
    float* ts = (float*)smem;                      // [prev*128 + cur], 64 KB
    __shared__ float s_wr[4];
    __shared__ float s_delta;

    int tid = threadIdx.x;

    for (int i = tid; i < KK * KK / 4; i += 256)
        ((float4*)ts)[i] = ((const float4*)trans)[i];
    __syncthreads();

    // Exact prune bound: Delta = max over cur of (max-min of trans[:,cur]) + margin
    if (tid < 128) {
        float mx = -3.4e38f, mn = 3.4e38f;
        #pragma unroll 8
        for (int p = 0; p < 128; p++) {
            float v = ts[p * 128 + tid];
            mx = fmaxf(mx, v); mn = fminf(mn, v);
        }
        float r = mx - mn;
        #pragma unroll
        for (int o = 16; o; o >>= 1) r = fmaxf(r, __shfl_xor_sync(0xffffffffu, r, o));
        if ((tid & 31) == 0) s_wr[tid >> 5] = r;
    }
    __syncthreads();
    if (tid == 0)
        s_delta = fmaxf(fmaxf(s_wr[0], s_wr[1]), fmaxf(s_wr[2], s_wr[3])) + 1e-3f;
    __syncthreads();
    float delta = s_delta;

    int w = tid >> 5, lane = tid & 31;
    int b = blockIdx.x * 8 + w;
    unsigned char* bp = (unsigned char*)(smem + 65536 + w * (TT * KK));       // 16 KB/warp
    uint2* cand = (uint2*)(smem + 65536 + 8 * TT * KK + w * 2112);            // 2 x 132 recs
    const float4* ts4 = (const float4*)ts;
    int last = warp_len(masks, b, lane) - 1;       // last >= 63

    const float4* fb4 = (const float4*)(feats + (size_t)b * TT * KK);  // 32 float4/row

    // t = 0: partition = feats[:,0,:] + trans[START,:]
    float4 f0  = fb4[lane];
    float4 tr0 = ((const float4*)(ts + START_TAG * KK))[lane];
    float v0 = f0.x + tr0.x, v1 = f0.y + tr0.y, v2 = f0.z + tr0.z, v3 = f0.w + tr0.w;
    float sv0 = v0, sv1 = v1, sv2 = v2, sv3 = v3;  // snapshot at t == last

    unsigned lmask = (1u << lane) - 1u;
    int p0 = lane * 4;

    // one Viterbi step (straight-line; no data-dependent control flow)
    auto step = [&](int t, float4 fc) {
        // warp max via bias trick: partitions > -12, so v+64 > 0 and raw float
        // bits are uint-monotone -> single REDUX, no encode/decode.
        float lm = fmaxf(fmaxf(v0, v1), fmaxf(v2, v3));
        unsigned mu = __reduce_max_sync(0xffffffffu, __float_as_uint(lm + 64.0f));
        float thr = (__uint_as_float(mu) - 64.0f) - delta;   // bias ulp << delta margin

        unsigned c0 = __ballot_sync(0xffffffffu, v0 >= thr);
        unsigned c1 = __ballot_sync(0xffffffffu, v1 >= thr);
        unsigned c2 = __ballot_sync(0xffffffffu, v2 >= thr);
        unsigned c3 = __ballot_sync(0xffffffffu, v3 >= thr);
        int n0 = __popc(c0), n01 = n0 + __popc(c1), n012 = n01 + __popc(c2);
        int ncand = n012 + __popc(c3);

        // compact candidates (pv, prev) into double-buffered SMEM staging
        // (comp-major order: prev = 0,4,..,124, then 1,5,.., ...)
        uint2* cb = cand + ((t & 1) ? 132 : 0);
        if ((c0 >> lane) & 1u) cb[       __popc(c0 & lmask)] = make_uint2(__float_as_uint(v0), p0 + 0);
        if ((c1 >> lane) & 1u) cb[n0   + __popc(c1 & lmask)] = make_uint2(__float_as_uint(v1), p0 + 1);
        if ((c2 >> lane) & 1u) cb[n01  + __popc(c2 & lmask)] = make_uint2(__float_as_uint(v2), p0 + 2);
        if ((c3 >> lane) & 1u) cb[n012 + __popc(c3 & lmask)] = make_uint2(__float_as_uint(v3), p0 + 3);
        if (lane < 7)          cb[ncand + lane] = make_uint2(0xFF7FFFFFu, 0);   // -FLT_MAX pads
        __syncwarp();

        float b0 = -3.4e38f, b1 = -3.4e38f, b2 = -3.4e38f, b3 = -3.4e38f;
        int   i0 = 0, i1 = 0, i2 = 0, i3 = 0;
        const uint4* cb4 = (const uint4*)cb;

        #define PROC(PVU, PREV)                                                      \
        {   float pv = __uint_as_float(PVU); int prev = (int)(PREV);                 \
            float4 tr = ts4[prev * 32 + lane];                                       \
            float q0 = (pv + tr.x) + fc.x; if (q0 > b0) { b0 = q0; i0 = prev; }      \
            float q1 = (pv + tr.y) + fc.y; if (q1 > b1) { b1 = q1; i1 = prev; }      \
            float q2 = (pv + tr.z) + fc.z; if (q2 > b2) { b2 = q2; i2 = prev; }      \
            float q3 = (pv + tr.w) + fc.w; if (q3 > b3) { b3 = q3; i3 = prev; }      \
        }
        // fast path: records 0-7 straight-line (covers ncand <= 8; pads inert)
        {
            uint4 ra = cb4[0], rb = cb4[1], rc = cb4[2], rd = cb4[3];
            PROC(ra.x, ra.y) PROC(ra.z, ra.w) PROC(rb.x, rb.y) PROC(rb.z, rb.w)
            PROC(rc.x, rc.y) PROC(rc.z, rc.w) PROC(rd.x, rd.y) PROC(rd.z, rd.w)
        }
        if (ncand > 8) {                           // warp-uniform, uncommon
            int ng = (ncand + 3) >> 2;
            for (int g = 2; g < ng; g++) {
                uint4 ra = cb4[2 * g], rb = cb4[2 * g + 1];
                PROC(ra.x, ra.y) PROC(ra.z, ra.w) PROC(rb.x, rb.y) PROC(rb.z, rb.w)
            }
        }
        #undef PROC

        // packed backpointers: byte for cur=c at bp[t*128 + c]
        ((unsigned*)(bp + t * KK))[lane] =
            (unsigned)i0 | ((unsigned)i1 << 8) | ((unsigned)i2 << 16) | ((unsigned)i3 << 24);

        v0 = b0; v1 = b1; v2 = b2; v3 = b3;
        bool atlast = (t == last);                 // predicated snapshot (off-chain)
        sv0 = atlast ? v0 : sv0; sv1 = atlast ? v1 : sv1;
        sv2 = atlast ? v2 : sv2; sv3 = atlast ? v3 : sv3;
    };

    // feat register ring, depth 4; refill clamped to row 127 (dup row, never consumed)
    float4 r0 = fb4[1 * 32 + lane], r1 = fb4[2 * 32 + lane];
    float4 r2 = fb4[3 * 32 + lane], r3 = fb4[4 * 32 + lane];

    #pragma unroll 1
    for (int tb = 1; tb <= 121; tb += 4) {
        int a4 = min(tb + 4, 127) * 32 + lane, a5 = min(tb + 5, 127) * 32 + lane;
        int a6 = min(tb + 6, 127) * 32 + lane, a7 = min(tb + 7, 127) * 32 + lane;
        float4 fa = r0;  r0 = fb4[a4]; step(tb + 0, fa);
        float4 fb_ = r1; r1 = fb4[a5]; step(tb + 1, fb_);
        float4 fcx = r2; r2 = fb4[a6]; step(tb + 2, fcx);
        float4 fd = r3;  r3 = fb4[a7]; step(tb + 3, fd);
    }
    step(125, r0); step(126, r1); step(127, r2);   // peeled tail (t = 1..127 total)

    // STOP transition argmax from snapshot (first-index ties)
    float q0 = sv0 + ts[(p0 + 0) * KK + STOP_TAG];
    float q1 = sv1 + ts[(p0 + 1) * KK + STOP_TAG];
    float q2 = sv2 + ts[(p0 + 2) * KK + STOP_TAG];
    float q3 = sv3 + ts[(p0 + 3) * KK + STOP_TAG];
    float bv = q0; int bi = p0;
    if (q1 > bv) { bv = q1; bi = p0 + 1; }
    if (q2 > bv) { bv = q2; bi = p0 + 2; }
    if (q3 > bv) { bv = q3; bi = p0 + 3; }
    #pragma unroll
    for (int o = 16; o; o >>= 1) {
        float ov = __shfl_xor_sync(0xffffffffu, bv, o);
        int   oi = __shfl_xor_sync(0xffffffffu, bi, o);
        if (ov > bv || (ov == bv && oi < bi)) { bv = ov; bi = oi; }
    }
    int cur = bi;   // warp-uniform

    if (out_score && lane == 0) out_score[b] = bv;

    if (out_dec) {
        float* od = out_dec + (size_t)b * TT;
        for (int t = last + 1 + lane; t < TT - 1; t += 32) od[t] = 0.0f;   // masked tail
        if (lane == 0) { od[TT - 1] = (float)cur; od[last] = (float)cur; } // ref quirk
        for (int t = last; t >= 1; t--) {
            cur = bp[t * KK + cur];                 // uniform SMEM pointer chase
            if (lane == 0) od[t - 1] = (float)cur;
        }
    }
}

// ---------------------------------------------------------------------------
extern "C" void kernel_launch(void* const* d_in, const int* in_sizes, int n_in,
                              void* d_out, int out_size) {
    const float* feats = nullptr;
    const float* trans = nullptr;
    const void*  masks = nullptr;
    for (int i = 0; i < n_in; i++) {
        if      (in_sizes[i] == BB * TT * KK) feats = (const float*)d_in[i];
        else if (in_sizes[i] == KK * KK)      trans = (const float*)d_in[i];
        else if (in_sizes[i] == BB * TT)      masks = d_in[i];
    }
    if (!feats || !trans || !masks) return;

    float* out   = (float*)d_out;
    float* score = nullptr;
    float* dec   = nullptr;
    if (out_size == BB * TT + BB) { score = out; dec = out + BB; }   // (path_score, decode)
    else if (out_size == BB * TT) { dec = out; }
    else if (out_size == BB)      { score = out; }
    else                          { score = out; if (out_size >= BB * TT + BB) dec = out + BB; }

    int smem_bytes = 65536 + 8 * TT * KK + 8 * 2112;   // trans + bp + staging = 213504
    cudaFuncSetAttribute(viterbi_kernel, cudaFuncAttributeMaxDynamicSharedMemorySize, smem_bytes);
    viterbi_kernel<<<BB / 8, 256, smem_bytes>>>(feats, trans, masks, score, dec);
}